// round 4
// baseline (speedup 1.0000x reference)
#include <cuda_runtime.h>

// Problem constants
constexpr int Bb   = 4;
constexpr int Ts   = 2048;
constexpr int Cc   = 1024;
constexpr int Hh   = 16;
constexpr int Dh   = 64;
constexpr int Mtot = Bb * Ts;      // 8192 rows
constexpr int Nqkv = 3 * Cc;       // 3072

// Scratch (device globals are the sanctioned scratch mechanism; no runtime allocs)
__device__ float g_qkv[(size_t)Mtot * Nqkv];   // 96 MB: [b*T+t][3*C] = [.., sel*C + h*Dh + d]
__device__ float g_att[(size_t)Mtot * Cc];     // 32 MB: [b*T+t][h*Dh + d]

// ---------------------------------------------------------------------------
// SGEMM: C[M,N] = A[M,K] @ B[K,N] + bias[N]
// 128x128 block tile, BK=8, 8x8 per-thread microtile, 256 threads.
// ---------------------------------------------------------------------------
template<int BM, int BN, int BK, int TM, int TN>
__global__ __launch_bounds__(256, 2)
void sgemm_bias_kernel(int M, int N, int K,
                       const float* __restrict__ A,
                       const float* __restrict__ Bm,
                       const float* __restrict__ bias,
                       float* __restrict__ Cm)
{
    __shared__ float As[BK][BM];   // A tile, K-major transposed for row-contig reads
    __shared__ float Bs[BK][BN];

    const int tid   = threadIdx.x;        // 256 threads: 16x16 microtile grid
    const int crow  = tid >> 4;           // 0..15  (M direction)
    const int ccol  = tid & 15;           // 0..15  (N direction)
    const int rowA0 = blockIdx.y * BM;
    const int colB0 = blockIdx.x * BN;

    // Global-load mapping (float4)
    const int aRow = tid >> 1;            // 0..127
    const int aCol = (tid & 1) * 4;       // 0 or 4 (BK=8)
    const int bRow = tid >> 5;            // 0..7
    const int bCol = (tid & 31) * 4;      // 0..124

    float acc[TM][TN];
#pragma unroll
    for (int i = 0; i < TM; i++)
#pragma unroll
        for (int j = 0; j < TN; j++) acc[i][j] = 0.f;

    const float* Ap = A  + (size_t)(rowA0 + aRow) * K + aCol;
    const float* Bp = Bm + (size_t)bRow * N + colB0 + bCol;

    for (int k0 = 0; k0 < K; k0 += BK) {
        float4 av = *(const float4*)(Ap + k0);
        As[aCol + 0][aRow] = av.x;
        As[aCol + 1][aRow] = av.y;
        As[aCol + 2][aRow] = av.z;
        As[aCol + 3][aRow] = av.w;
        *(float4*)&Bs[bRow][bCol] = *(const float4*)(Bp + (size_t)k0 * N);
        __syncthreads();

#pragma unroll
        for (int kk = 0; kk < BK; kk++) {
            float ar[TM], br[TN];
            *(float4*)&ar[0] = *(const float4*)&As[kk][crow * TM + 0];
            *(float4*)&ar[4] = *(const float4*)&As[kk][crow * TM + 4];
            *(float4*)&br[0] = *(const float4*)&Bs[kk][ccol * TN + 0];
            *(float4*)&br[4] = *(const float4*)&Bs[kk][ccol * TN + 4];
#pragma unroll
            for (int i = 0; i < TM; i++)
#pragma unroll
                for (int j = 0; j < TN; j++)
                    acc[i][j] = fmaf(ar[i], br[j], acc[i][j]);
        }
        __syncthreads();
    }

#pragma unroll
    for (int i = 0; i < TM; i++) {
        size_t r = (size_t)rowA0 + crow * TM + i;
#pragma unroll
        for (int j = 0; j < TN; j += 4) {
            int c = colB0 + ccol * TN + j;
            float4 o;
            o.x = acc[i][j + 0] + bias[c + 0];
            o.y = acc[i][j + 1] + bias[c + 1];
            o.z = acc[i][j + 2] + bias[c + 2];
            o.w = acc[i][j + 3] + bias[c + 3];
            *(float4*)(Cm + r * N + c) = o;
        }
    }
}

// ---------------------------------------------------------------------------
// Flash attention, fp32, causal. One block per (b, h, 64-row q tile).
// 256 threads as 16x16; each thread owns a 4x4 microtile of the 64x64 S / O.
// Smem: Qt[d][r], KP[ ][ ] (K transposed, reused as P natural), Vs[c][d].
// Exactly 48 KB static -> 2 blocks/SM.
// ---------------------------------------------------------------------------
__global__ __launch_bounds__(256, 2)
void flash_attn_kernel()
{
    __shared__ float Qt[Dh][64];   // Q^T, pre-scaled by 1/sqrt(Dh)
    __shared__ float KP[64][64];   // phase 1: K^T [d][c]; phase 2: P [r][c]
    __shared__ float Vs[64][64];   // V natural [c][d]

    const int tid = threadIdx.x;
    const int qt  = blockIdx.x;
    const int h   = blockIdx.y;
    const int b   = blockIdx.z;
    const int q0  = qt * 64;
    const int ty  = tid >> 4;      // row group 0..15
    const int tx  = tid & 15;      // col group 0..15

    const int tr  = tid >> 2;      // tile-load row 0..63
    const int tdg = tid & 3;       // tile-load d group

    const float scale = 0.125f;    // 1/sqrt(64)

    // Load Q transposed + pre-scaled
    {
        const float* qg = g_qkv + (size_t)(b * Ts + q0 + tr) * Nqkv + h * Dh;
#pragma unroll
        for (int l = 0; l < 4; l++) {
            int d = (tdg + l * 4) * 4;
            float4 v = *(const float4*)(qg + d);
            Qt[d + 0][tr] = v.x * scale;
            Qt[d + 1][tr] = v.y * scale;
            Qt[d + 2][tr] = v.z * scale;
            Qt[d + 3][tr] = v.w * scale;
        }
    }

    float m[4], l[4], o[4][4];
#pragma unroll
    for (int i = 0; i < 4; i++) {
        m[i] = -1e30f; l[i] = 0.f;
#pragma unroll
        for (int j = 0; j < 4; j++) o[i][j] = 0.f;
    }

    for (int kt = 0; kt <= qt; kt++) {
        const int k0 = kt * 64;
        __syncthreads();  // prev-iter PV readers done (also fences Qt on iter 0)

        // Load K^T and V tiles
        {
            const float* kg = g_qkv + (size_t)(b * Ts + k0 + tr) * Nqkv + Cc + h * Dh;
            const float* vg = kg + Cc;
#pragma unroll
            for (int ll = 0; ll < 4; ll++) {
                int d = (tdg + ll * 4) * 4;
                float4 kv = *(const float4*)(kg + d);
                KP[d + 0][tr] = kv.x;
                KP[d + 1][tr] = kv.y;
                KP[d + 2][tr] = kv.z;
                KP[d + 3][tr] = kv.w;
                *(float4*)&Vs[tr][d] = *(const float4*)(vg + d);
            }
        }
        __syncthreads();

        // S = (Q*scale) @ K^T   (64x64, 4x4 per thread)
        float s[4][4];
#pragma unroll
        for (int i = 0; i < 4; i++)
#pragma unroll
            for (int j = 0; j < 4; j++) s[i][j] = 0.f;

#pragma unroll 8
        for (int d = 0; d < Dh; d++) {
            float4 qv = *(const float4*)&Qt[d][ty * 4];
            float4 kv = *(const float4*)&KP[d][tx * 4];
            float qa[4] = {qv.x, qv.y, qv.z, qv.w};
            float ka[4] = {kv.x, kv.y, kv.z, kv.w};
#pragma unroll
            for (int i = 0; i < 4; i++)
#pragma unroll
                for (int j = 0; j < 4; j++)
                    s[i][j] = fmaf(qa[i], ka[j], s[i][j]);
        }

        // Causal mask on the diagonal tile (finite sentinel avoids inf-inf NaN)
        if (kt == qt) {
#pragma unroll
            for (int i = 0; i < 4; i++)
#pragma unroll
                for (int j = 0; j < 4; j++)
                    if (tx * 4 + j > ty * 4 + i) s[i][j] = -1e30f;
        }

        // Online softmax update (row reductions across the 16 tx lanes)
        float p[4][4];
#pragma unroll
        for (int i = 0; i < 4; i++) {
            float mx = fmaxf(fmaxf(s[i][0], s[i][1]), fmaxf(s[i][2], s[i][3]));
#pragma unroll
            for (int off = 8; off >= 1; off >>= 1)
                mx = fmaxf(mx, __shfl_xor_sync(0xffffffffu, mx, off));
            float mn = fmaxf(m[i], mx);
            float f  = __expf(m[i] - mn);
            m[i] = mn;
            float rs = 0.f;
#pragma unroll
            for (int j = 0; j < 4; j++) { p[i][j] = __expf(s[i][j] - mn); rs += p[i][j]; }
#pragma unroll
            for (int off = 8; off >= 1; off >>= 1)
                rs += __shfl_xor_sync(0xffffffffu, rs, off);
            l[i] = l[i] * f + rs;
#pragma unroll
            for (int j = 0; j < 4; j++) o[i][j] *= f;
        }

        __syncthreads();  // everyone done reading KP as K^T

        // Stash P into KP (natural layout [r][c])
#pragma unroll
        for (int i = 0; i < 4; i++)
            *(float4*)&KP[ty * 4 + i][tx * 4] =
                make_float4(p[i][0], p[i][1], p[i][2], p[i][3]);
        __syncthreads();

        // O += P @ V
#pragma unroll 8
        for (int c = 0; c < 64; c++) {
            float4 vv = *(const float4*)&Vs[c][tx * 4];
            float va[4] = {vv.x, vv.y, vv.z, vv.w};
            float pa[4];
#pragma unroll
            for (int i = 0; i < 4; i++) pa[i] = KP[ty * 4 + i][c];
#pragma unroll
            for (int i = 0; i < 4; i++)
#pragma unroll
                for (int j = 0; j < 4; j++)
                    o[i][j] = fmaf(pa[i], va[j], o[i][j]);
        }
    }

    // Epilogue: normalize and write attention output [b*T+t][h*Dh + d]
#pragma unroll
    for (int i = 0; i < 4; i++) {
        float inv = 1.0f / l[i];
        size_t r = (size_t)(b * Ts + q0 + ty * 4 + i) * Cc + h * Dh + tx * 4;
        *(float4*)(g_att + r) =
            make_float4(o[i][0] * inv, o[i][1] * inv, o[i][2] * inv, o[i][3] * inv);
    }
}

// ---------------------------------------------------------------------------
// Launch: QKV GEMM -> flash attention -> output GEMM. Graph-capturable.
// ---------------------------------------------------------------------------
extern "C" void kernel_launch(void* const* d_in, const int* in_sizes, int n_in,
                              void* d_out, int out_size)
{
    const float* x     = (const float*)d_in[0];
    const float* w_qkv = (const float*)d_in[1];
    const float* b_qkv = (const float*)d_in[2];
    const float* w_out = (const float*)d_in[3];
    const float* b_out = (const float*)d_in[4];
    float* out = (float*)d_out;

    float *qkv_ptr = nullptr, *att_ptr = nullptr;
    cudaGetSymbolAddress((void**)&qkv_ptr, g_qkv);
    cudaGetSymbolAddress((void**)&att_ptr, g_att);

    // 1) QKV projection: [8192,1024] @ [1024,3072] + bias
    {
        dim3 grid(Nqkv / 128, Mtot / 128);
        sgemm_bias_kernel<128, 128, 8, 8, 8><<<grid, 256>>>(
            Mtot, Nqkv, Cc, x, w_qkv, b_qkv, qkv_ptr);
    }

    // 2) Causal flash attention
    {
        dim3 grid(Ts / 64, Hh, Bb);
        flash_attn_kernel<<<grid, 256>>>();
    }

    // 3) Output projection: [8192,1024] @ [1024,1024] + bias
    {
        dim3 grid(Cc / 128, Mtot / 128);
        sgemm_bias_kernel<128, 128, 8, 8, 8><<<grid, 256>>>(
            Mtot, Cc, Cc, att_ptr, w_out, b_out, out);
    }
}